// round 11
// baseline (speedup 1.0000x reference)
#include <cuda_runtime.h>
#include <cuda_fp16.h>
#include <cstdint>
#include <cstddef>

// ---------------------------------------------------------------------------
// SAGEConv: gather+mean-agg -> concat -> Linear(1024->512)+ReLU -> BatchNorm
//           -> row L2 normalize.
// R9: agg accumulates in packed fp16 (HADD2, dual accumulators) -> L2-bound;
//     single-pass fp16 HMMA GEMM, BN stats fused in GEMM epilogue.
// ---------------------------------------------------------------------------

#define DD      512
#define KK      1024
#define NMAX    20000
#define NTOT    40000
#define NPAD    20096           // 157 * 128
#define MAXBLK  640

// ------------------------- device scratch (no mallocs) ---------------------
__device__ __align__(16) __half g_F16[(size_t)NTOT * DD];   // fp16 features 41 MB
__device__ __align__(16) __half g_A  [(size_t)NPAD * KK];   // concat fp16   41 MB
__device__ __align__(16) __half g_W16[(size_t)DD * KK];     // fp16 W         1 MB
__device__ __align__(16) float g_H[(size_t)NMAX * DD];      // post-ReLU     41 MB
__device__ float g_psum  [MAXBLK * DD];
__device__ float g_psumsq[MAXBLK * DD];
__device__ __align__(16) float g_scale[DD];
__device__ __align__(16) float g_shift[DD];
__device__ int   g_idx_is64;

// ------------------------- helpers -----------------------------------------
__device__ __forceinline__ uint32_t smem_u32(const void* p) {
    uint32_t a;
    asm("{ .reg .u64 t; cvta.to.shared.u64 t, %1; cvt.u32.u64 %0, t; }"
        : "=r"(a) : "l"(p));
    return a;
}
__device__ __forceinline__ void cpasync16(uint32_t dst, const void* src) {
    asm volatile("cp.async.cg.shared.global [%0], [%1], 16;"
                 :: "r"(dst), "l"(src) : "memory");
}
__device__ __forceinline__ void cp_commit() {
    asm volatile("cp.async.commit_group;" ::: "memory");
}
__device__ __forceinline__ void ldsm4(uint32_t& r0, uint32_t& r1,
                                      uint32_t& r2, uint32_t& r3, uint32_t a) {
    asm volatile("ldmatrix.sync.aligned.m8n8.x4.shared.b16 {%0,%1,%2,%3}, [%4];"
                 : "=r"(r0), "=r"(r1), "=r"(r2), "=r"(r3) : "r"(a));
}
__device__ __forceinline__ void mma16816(float* d, const uint32_t* a,
                                         const uint32_t* b) {
    asm volatile(
        "mma.sync.aligned.m16n8k16.row.col.f32.f16.f16.f32 "
        "{%0,%1,%2,%3}, {%4,%5,%6,%7}, {%8,%9}, {%0,%1,%2,%3};"
        : "+f"(d[0]), "+f"(d[1]), "+f"(d[2]), "+f"(d[3])
        : "r"(a[0]), "r"(a[1]), "r"(a[2]), "r"(a[3]), "r"(b[0]), "r"(b[1]));
}
__device__ __forceinline__ uint32_t packh2(float x0, float x1) {
    __half2 h = __floats2half2_rn(x0, x1);
    return *reinterpret_cast<uint32_t*>(&h);
}

// ------------------------- index dtype detection ---------------------------
__global__ void detect_idx_kernel(const unsigned int* __restrict__ p, int n) {
    __shared__ unsigned int red[256];
    unsigned int acc = 0;
    for (int i = threadIdx.x; i < n; i += blockDim.x)
        if (i & 1) acc |= p[i];
    red[threadIdx.x] = acc;
    __syncthreads();
    for (int s = 128; s > 0; s >>= 1) {
        if (threadIdx.x < s) red[threadIdx.x] |= red[threadIdx.x + s];
        __syncthreads();
    }
    if (threadIdx.x == 0) g_idx_is64 = (red[0] == 0u) ? 1 : 0;
}
__device__ __forceinline__ long long load_idx(const void* p, size_t i, int is64) {
    if (is64) return ((const long long*)p)[i];
    return (long long)((const int*)p)[i];
}

// ------------------------- kernel 0: features f32 -> fp16 ------------------
__global__ __launch_bounds__(256)
void fconv_kernel(const float4* __restrict__ feat4, int total8) {
    const int i = blockIdx.x * 256 + threadIdx.x;
    if (i >= total8) return;
    const float4 v0 = feat4[2 * i];
    const float4 v1 = feat4[2 * i + 1];
    uint4 o;
    o.x = packh2(v0.x, v0.y);
    o.y = packh2(v0.z, v0.w);
    o.z = packh2(v1.x, v1.y);
    o.w = packh2(v1.z, v1.w);
    ((uint4*)g_F16)[i] = o;
}

// ------------------------- kernel 1: gather(fp16) + mean agg ---------------
// 256 threads = 4 rows x 64 lanes; each lane owns 16B (8 halves).
// Accumulation in packed fp16 (HADD2), dual accumulators, fp32 final combine.
__global__ __launch_bounds__(256)
void agg_kernel(const void* __restrict__ self_idx,
                const void* __restrict__ neigh_idx,
                int N, int S) {
    const int rg   = threadIdx.x >> 6;    // 0..3 row-in-block
    const int lane = threadIdx.x & 63;    // 16B column
    const int n    = blockIdx.x * 4 + rg;
    __shared__ int sidx[4][33];
    const int is64 = g_idx_is64;

    for (int i = threadIdx.x; i < 4 * S; i += 256) {
        const int r = i / S, s = i - r * S;
        const int row = blockIdx.x * 4 + r;
        if (row < N)
            sidx[r][s] = (int)load_idx(neigh_idx, (size_t)row * S + s, is64);
    }
    if (threadIdx.x < 4) {
        const int row = blockIdx.x * 4 + threadIdx.x;
        if (row < N)
            sidx[threadIdx.x][S] = (int)load_idx(self_idx, row, is64);
    }
    __syncthreads();
    if (n >= N) return;

    const char* F = (const char*)g_F16;
    const uint32_t lo = (uint32_t)(lane << 4);
    uint4* A4 = reinterpret_cast<uint4*>(g_A);

    // self half (cols 0..511): straight 16B copy
    A4[(size_t)n * 128 + lane] =
        *(const uint4*)(F + (((uint32_t)sidx[rg][S] << 10) | lo));

    // aggregated half: packed fp16 accumulate, two interleaved accumulators
    const __half2 z = __float2half2_rn(0.f);
    __half2 aA0 = z, aA1 = z, aA2 = z, aA3 = z;
    __half2 aB0 = z, aB1 = z, aB2 = z, aB3 = z;
    int s = 0;
    for (; s + 1 < S; s += 2) {
        const uint4 va = *(const uint4*)(F + (((uint32_t)sidx[rg][s] << 10) | lo));
        const uint4 vb = *(const uint4*)(F + (((uint32_t)sidx[rg][s + 1] << 10) | lo));
        aA0 = __hadd2(aA0, *reinterpret_cast<const __half2*>(&va.x));
        aA1 = __hadd2(aA1, *reinterpret_cast<const __half2*>(&va.y));
        aA2 = __hadd2(aA2, *reinterpret_cast<const __half2*>(&va.z));
        aA3 = __hadd2(aA3, *reinterpret_cast<const __half2*>(&va.w));
        aB0 = __hadd2(aB0, *reinterpret_cast<const __half2*>(&vb.x));
        aB1 = __hadd2(aB1, *reinterpret_cast<const __half2*>(&vb.y));
        aB2 = __hadd2(aB2, *reinterpret_cast<const __half2*>(&vb.z));
        aB3 = __hadd2(aB3, *reinterpret_cast<const __half2*>(&vb.w));
    }
    if (s < S) {
        const uint4 va = *(const uint4*)(F + (((uint32_t)sidx[rg][s] << 10) | lo));
        aA0 = __hadd2(aA0, *reinterpret_cast<const __half2*>(&va.x));
        aA1 = __hadd2(aA1, *reinterpret_cast<const __half2*>(&va.y));
        aA2 = __hadd2(aA2, *reinterpret_cast<const __half2*>(&va.z));
        aA3 = __hadd2(aA3, *reinterpret_cast<const __half2*>(&va.w));
    }
    // fp32 combine + scale
    const float inv = 1.0f / (float)S;
    float2 fa, fb;
    uint4 o;
    fa = __half22float2(aA0); fb = __half22float2(aB0);
    o.x = packh2((fa.x + fb.x) * inv, (fa.y + fb.y) * inv);
    fa = __half22float2(aA1); fb = __half22float2(aB1);
    o.y = packh2((fa.x + fb.x) * inv, (fa.y + fb.y) * inv);
    fa = __half22float2(aA2); fb = __half22float2(aB2);
    o.z = packh2((fa.x + fb.x) * inv, (fa.y + fb.y) * inv);
    fa = __half22float2(aA3); fb = __half22float2(aB3);
    o.w = packh2((fa.x + fb.x) * inv, (fa.y + fb.y) * inv);
    A4[(size_t)n * 128 + 64 + lane] = o;
}

// ------------------------- kernel 1b: W f32 -> fp16 ------------------------
__global__ __launch_bounds__(256)
void wconv_kernel(const float* __restrict__ W) {
    const int i = blockIdx.x * 256 + threadIdx.x;    // over DD*KK/8
    const float4 v0 = *(const float4*)(W + (size_t)i * 8);
    const float4 v1 = *(const float4*)(W + (size_t)i * 8 + 4);
    uint4 o;
    o.x = packh2(v0.x, v0.y);
    o.y = packh2(v0.z, v0.w);
    o.z = packh2(v1.x, v1.y);
    o.w = packh2(v1.z, v1.w);
    ((uint4*)g_W16)[i] = o;
}

// ------------------------- kernel 2: HMMA GEMM + bias + ReLU + BN partials -
#define SASTRIDE 80
#define VARB     10240
#define STAGEB   (2 * VARB)
#define NSTAGE   3
#define HDRB     1024
#define GEMM_SMEM (HDRB + NSTAGE * STAGEB)   // 62464 -> 2 CTAs/SM

__global__ __launch_bounds__(256, 2)
void gemm_tc_kernel(const float* __restrict__ bias, int M) {
    extern __shared__ char smem[];
    const uint32_t sb = smem_u32(smem);
    const int tid  = threadIdx.x;
    const int wid  = tid >> 5;
    const int lane = tid & 31;
    const int wm   = wid >> 2;
    const int wn   = wid & 3;
    const int m0 = blockIdx.y * 128;
    const int n0 = blockIdx.x * 128;

    float* bsm = (float*)smem;
    if (tid < 128) bsm[tid] = bias[n0 + tid];

    const uint32_t aOff = (uint32_t)((lane & 15) * SASTRIDE + (lane >> 4) * 16);
    const uint32_t bOff = (uint32_t)(((lane & 7) + ((lane >> 4) << 3)) * SASTRIDE
                                     + (((lane >> 3) & 1) << 4));

    const char* pA = (const char*)g_A;
    const char* pW = (const char*)g_W16;

    auto load_chunk = [&](int stage, int kc) {
        const uint32_t base = sb + HDRB + stage * STAGEB;
        #pragma unroll
        for (int i = 0; i < 2; ++i) {
            const int idx = tid + (i << 8);
            const int r = idx >> 2, c = idx & 3;
            const uint32_t dst = base + (uint32_t)(r * SASTRIDE + c * 16);
            const size_t sa  = ((size_t)(m0 + r) << 11) + (size_t)(kc * 64 + c * 16);
            const size_t sbo = ((size_t)(n0 + r) << 11) + (size_t)(kc * 64 + c * 16);
            cpasync16(dst,        pA + sa);
            cpasync16(dst + VARB, pW + sbo);
        }
        cp_commit();
    };

    float acc[4][4][4];
    #pragma unroll
    for (int i = 0; i < 4; ++i)
        #pragma unroll
        for (int j = 0; j < 4; ++j)
            #pragma unroll
            for (int q = 0; q < 4; ++q) acc[i][j][q] = 0.f;

    load_chunk(0, 0);
    load_chunk(1, 1);

    const int NKC = KK / 32;
    for (int kc = 0; kc < NKC; ++kc) {
        asm volatile("cp.async.wait_group 1;" ::: "memory");
        __syncthreads();

        if (kc + 2 < NKC) load_chunk((kc + 2) % 3, kc + 2);
        else              cp_commit();

        const uint32_t st = sb + HDRB + (kc % 3) * STAGEB;
        const uint32_t bufA = st;
        const uint32_t bufB = st + VARB;

        #pragma unroll
        for (int k16 = 0; k16 < 2; ++k16) {
            const uint32_t kb = (uint32_t)(k16 * 32);
            uint32_t a[4][4], bfr[2][4];
            #pragma unroll
            for (int j2 = 0; j2 < 2; ++j2) {
                const uint32_t ro = (uint32_t)((wn * 32 + j2 * 16) * SASTRIDE) + kb;
                ldsm4(bfr[j2][0], bfr[j2][1], bfr[j2][2], bfr[j2][3], bufB + ro + bOff);
            }
            #pragma unroll
            for (int im = 0; im < 4; ++im) {
                const uint32_t ro = (uint32_t)((wm * 64 + im * 16) * SASTRIDE) + kb;
                ldsm4(a[im][0], a[im][1], a[im][2], a[im][3], bufA + ro + aOff);
            }
            #pragma unroll
            for (int im = 0; im < 4; ++im)
                #pragma unroll
                for (int jn = 0; jn < 4; ++jn)
                    mma16816(acc[im][jn], a[im], &bfr[jn >> 1][(jn & 1) * 2]);
        }
    }

    // ---- epilogue: bias + relu -> g_H, plus BN partial sums (fused) ----
    __syncthreads();
    float* psum = (float*)(smem + HDRB);            // [128 cols][16 slots]
    float* psq  = (float*)(smem + HDRB + 8192);
    const int g    = lane >> 2;
    const int tq   = lane & 3;
    const int slot = wm * 8 + g;

    #pragma unroll
    for (int jn = 0; jn < 4; ++jn) {
        const int colL = wn * 32 + jn * 8 + tq * 2;
        const float b0 = bsm[colL], b1 = bsm[colL + 1];
        float s0 = 0.f, s1 = 0.f, q0 = 0.f, q1 = 0.f;
        #pragma unroll
        for (int im = 0; im < 4; ++im) {
            const int row0 = m0 + wm * 64 + im * 16 + g;
            float v0 = acc[im][jn][0] + b0;
            float v1 = acc[im][jn][1] + b1;
            float v2 = acc[im][jn][2] + b0;
            float v3 = acc[im][jn][3] + b1;
            v0 = v0 > 0.f ? v0 : 0.f;
            v1 = v1 > 0.f ? v1 : 0.f;
            v2 = v2 > 0.f ? v2 : 0.f;
            v3 = v3 > 0.f ? v3 : 0.f;
            const int col = n0 + colL;
            if (row0 < M) {
                *(float2*)(g_H + (size_t)row0 * DD + col) = make_float2(v0, v1);
                s0 += v0; s1 += v1; q0 += v0 * v0; q1 += v1 * v1;
            }
            if (row0 + 8 < M) {
                *(float2*)(g_H + (size_t)(row0 + 8) * DD + col) = make_float2(v2, v3);
                s0 += v2; s1 += v3; q0 += v2 * v2; q1 += v3 * v3;
            }
        }
        psum[colL * 16 + slot]       = s0;
        psum[(colL + 1) * 16 + slot] = s1;
        psq [colL * 16 + slot]       = q0;
        psq [(colL + 1) * 16 + slot] = q1;
    }
    __syncthreads();

    {
        const int col = tid & 127;
        const float* src = (tid & 128) ? psq : psum;
        float s = 0.f;
        #pragma unroll
        for (int k = 0; k < 16; ++k) s += src[col * 16 + k];
        float* dstg = (tid & 128) ? g_psumsq : g_psum;
        dstg[blockIdx.y * DD + n0 + col] = s;
    }
}

// ------------------------- BN finalize -------------------------------------
__global__ __launch_bounds__(256)
void finalize_stats(const float* __restrict__ gamma,
                    const float* __restrict__ beta, int M, int nblk) {
    const int col  = blockIdx.x * 8 + (threadIdx.x >> 5);
    const int lane = threadIdx.x & 31;
    float s = 0.f, q = 0.f;
    for (int i = lane; i < nblk; i += 32) {
        s += g_psum  [i * DD + col];
        q += g_psumsq[i * DD + col];
    }
    #pragma unroll
    for (int o = 16; o > 0; o >>= 1) {
        s += __shfl_xor_sync(0xffffffffu, s, o);
        q += __shfl_xor_sync(0xffffffffu, q, o);
    }
    if (lane == 0) {
        const float invM = 1.0f / (float)M;
        const float mean = s * invM;
        const float var  = q * invM - mean * mean;
        const float rstd = rsqrtf(var + 1e-5f);
        const float sc = rstd * gamma[col];
        g_scale[col] = sc;
        g_shift[col] = beta[col] - mean * sc;
    }
}

// ------------------------- kernel 4: BN apply + row L2 normalize -----------
// 2 rows per 256-thread block
__global__ __launch_bounds__(256)
void bn_l2_kernel(float4* __restrict__ out4, int M) {
    const int rg = threadIdx.x >> 7;      // 0..1 row-in-block
    const int t  = threadIdx.x & 127;
    const int n  = blockIdx.x * 2 + rg;
    const bool act = (n < M);

    const float4* H4  = reinterpret_cast<const float4*>(g_H);
    const float4* sc4 = reinterpret_cast<const float4*>(g_scale);
    const float4* sh4 = reinterpret_cast<const float4*>(g_shift);

    float4 y = make_float4(0.f, 0.f, 0.f, 0.f);
    if (act) {
        float4 h  = H4[(size_t)n * 128 + t];
        float4 sc = sc4[t];
        float4 sh = sh4[t];
        y.x = h.x * sc.x + sh.x;
        y.y = h.y * sc.y + sh.y;
        y.z = h.z * sc.z + sh.z;
        y.w = h.w * sc.w + sh.w;
    }

    float ss = y.x * y.x + y.y * y.y + y.z * y.z + y.w * y.w;
    #pragma unroll
    for (int o = 16; o > 0; o >>= 1)
        ss += __shfl_xor_sync(0xffffffffu, ss, o);

    __shared__ float ws[2][4];
    if ((t & 31) == 0) ws[rg][t >> 5] = ss;
    __syncthreads();
    const float tot = ws[rg][0] + ws[rg][1] + ws[rg][2] + ws[rg][3];
    const float inv = 1.0f / (sqrtf(tot) + 1e-6f);

    if (act) {
        y.x *= inv; y.y *= inv; y.z *= inv; y.w *= inv;
        out4[(size_t)n * 128 + t] = y;
    }
}

// ------------------------- launcher ----------------------------------------
extern "C" void kernel_launch(void* const* d_in, const int* in_sizes, int n_in,
                              void* d_out, int out_size) {
    const float* features = (const float*)d_in[0];
    const float* W        = (const float*)d_in[1];
    const float* b        = (const float*)d_in[2];
    const float* gamma    = (const float*)d_in[3];
    const float* beta     = (const float*)d_in[4];
    const void*  self_idx = d_in[5];
    const void*  neigh_idx= d_in[6];

    const int N = in_sizes[5];
    const int S = in_sizes[6] / N;
    const int total8 = in_sizes[0] / 8;

    cudaFuncSetAttribute(gemm_tc_kernel,
                         cudaFuncAttributeMaxDynamicSharedMemorySize, GEMM_SMEM);

    detect_idx_kernel<<<1, 256>>>((const unsigned int*)self_idx, N);
    fconv_kernel<<<(total8 + 255) / 256, 256>>>((const float4*)features, total8);
    wconv_kernel<<<(DD * KK / 8) / 256, 256>>>(W);
    agg_kernel<<<(N + 3) / 4, 256>>>(self_idx, neigh_idx, N, S);

    dim3 ggrid(DD / 128, (N + 127) / 128);
    gemm_tc_kernel<<<ggrid, 256, GEMM_SMEM>>>(b, N);

    const int nblk = (N + 127) / 128;
    finalize_stats<<<64, 256>>>(gamma, beta, N, nblk);

    bn_l2_kernel<<<(N + 1) / 2, 256>>>((float4*)d_out, N);
}

// round 12
// speedup vs baseline: 1.3242x; 1.3242x over previous
#include <cuda_runtime.h>
#include <cuda_fp16.h>
#include <cstdint>
#include <cstddef>

// ---------------------------------------------------------------------------
// SAGEConv: gather+mean-agg -> concat -> Linear(1024->512)+ReLU -> BatchNorm
//           -> row L2 normalize.
// R12: R8 base (f32-accum agg). agg: 1 warp/row, 32B/lane (2x MLP).
//      H stored fp16. Single-pass fp16 HMMA GEMM + fused BN stats.
// ---------------------------------------------------------------------------

#define DD      512
#define KK      1024
#define NMAX    20000
#define NTOT    40000
#define NPAD    20096           // 157 * 128
#define MAXBLK  640

// ------------------------- device scratch (no mallocs) ---------------------
__device__ __align__(16) __half g_F16[(size_t)NTOT * DD];   // fp16 features 41 MB
__device__ __align__(16) __half g_A  [(size_t)NPAD * KK];   // concat fp16   41 MB
__device__ __align__(16) __half g_W16[(size_t)DD * KK];     // fp16 W         1 MB
__device__ __align__(16) __half g_Hh[(size_t)NMAX * DD];    // post-ReLU fp16 20 MB
__device__ float g_psum  [MAXBLK * DD];
__device__ float g_psumsq[MAXBLK * DD];
__device__ __align__(16) float g_scale[DD];
__device__ __align__(16) float g_shift[DD];
__device__ int   g_idx_is64;

// ------------------------- helpers -----------------------------------------
__device__ __forceinline__ uint32_t smem_u32(const void* p) {
    uint32_t a;
    asm("{ .reg .u64 t; cvta.to.shared.u64 t, %1; cvt.u32.u64 %0, t; }"
        : "=r"(a) : "l"(p));
    return a;
}
__device__ __forceinline__ void cpasync16(uint32_t dst, const void* src) {
    asm volatile("cp.async.cg.shared.global [%0], [%1], 16;"
                 :: "r"(dst), "l"(src) : "memory");
}
__device__ __forceinline__ void cp_commit() {
    asm volatile("cp.async.commit_group;" ::: "memory");
}
__device__ __forceinline__ void ldsm4(uint32_t& r0, uint32_t& r1,
                                      uint32_t& r2, uint32_t& r3, uint32_t a) {
    asm volatile("ldmatrix.sync.aligned.m8n8.x4.shared.b16 {%0,%1,%2,%3}, [%4];"
                 : "=r"(r0), "=r"(r1), "=r"(r2), "=r"(r3) : "r"(a));
}
__device__ __forceinline__ void mma16816(float* d, const uint32_t* a,
                                         const uint32_t* b) {
    asm volatile(
        "mma.sync.aligned.m16n8k16.row.col.f32.f16.f16.f32 "
        "{%0,%1,%2,%3}, {%4,%5,%6,%7}, {%8,%9}, {%0,%1,%2,%3};"
        : "+f"(d[0]), "+f"(d[1]), "+f"(d[2]), "+f"(d[3])
        : "r"(a[0]), "r"(a[1]), "r"(a[2]), "r"(a[3]), "r"(b[0]), "r"(b[1]));
}
__device__ __forceinline__ uint32_t packh2(float x0, float x1) {
    __half2 h = __floats2half2_rn(x0, x1);
    return *reinterpret_cast<uint32_t*>(&h);
}

// ------------------------- index dtype detection ---------------------------
__global__ void detect_idx_kernel(const unsigned int* __restrict__ p, int n) {
    __shared__ unsigned int red[256];
    unsigned int acc = 0;
    for (int i = threadIdx.x; i < n; i += blockDim.x)
        if (i & 1) acc |= p[i];
    red[threadIdx.x] = acc;
    __syncthreads();
    for (int s = 128; s > 0; s >>= 1) {
        if (threadIdx.x < s) red[threadIdx.x] |= red[threadIdx.x + s];
        __syncthreads();
    }
    if (threadIdx.x == 0) g_idx_is64 = (red[0] == 0u) ? 1 : 0;
}
__device__ __forceinline__ long long load_idx(const void* p, size_t i, int is64) {
    if (is64) return ((const long long*)p)[i];
    return (long long)((const int*)p)[i];
}

// ------------------------- kernel 0: features f32 -> fp16 ------------------
__global__ __launch_bounds__(256)
void fconv_kernel(const float4* __restrict__ feat4, int total8) {
    const int i = blockIdx.x * 256 + threadIdx.x;
    if (i >= total8) return;
    const float4 v0 = feat4[2 * i];
    const float4 v1 = feat4[2 * i + 1];
    uint4 o;
    o.x = packh2(v0.x, v0.y);
    o.y = packh2(v0.z, v0.w);
    o.z = packh2(v1.x, v1.y);
    o.w = packh2(v1.z, v1.w);
    ((uint4*)g_F16)[i] = o;
}

// ------------------------- kernel 1: gather(fp16) + mean agg ---------------
// 256 threads = 8 warps; one warp per output row; each lane owns 32B
// (two independent uint4 loads per neighbor -> 2x MLP). f32 accumulate.
__global__ __launch_bounds__(256)
void agg_kernel(const void* __restrict__ self_idx,
                const void* __restrict__ neigh_idx,
                int N, int S) {
    const int rg   = threadIdx.x >> 5;    // 0..7 row-in-block (= warp)
    const int lane = threadIdx.x & 31;    // owns bytes [lane*32, lane*32+32)
    const int n    = blockIdx.x * 8 + rg;
    __shared__ int sidx[8][33];
    const int is64 = g_idx_is64;

    for (int i = threadIdx.x; i < 8 * S; i += 256) {
        const int r = i / S, s = i - r * S;
        const int row = blockIdx.x * 8 + r;
        if (row < N)
            sidx[r][s] = (int)load_idx(neigh_idx, (size_t)row * S + s, is64);
    }
    if (threadIdx.x < 8) {
        const int row = blockIdx.x * 8 + threadIdx.x;
        if (row < N)
            sidx[threadIdx.x][S] = (int)load_idx(self_idx, row, is64);
    }
    __syncthreads();
    if (n >= N) return;

    const char* F = (const char*)g_F16;
    const uint32_t lo = (uint32_t)(lane << 5);
    uint4* A4 = reinterpret_cast<uint4*>(g_A);

    // self half (cols 0..511): straight 32B copy
    {
        const uint32_t base = ((uint32_t)sidx[rg][S] << 10) | lo;
        A4[(size_t)n * 128 + 2 * lane]     = *(const uint4*)(F + base);
        A4[(size_t)n * 128 + 2 * lane + 1] = *(const uint4*)(F + base + 16);
    }

    // aggregated half: f32 accumulate of fp16 reads, 2 loads in flight
    float a[16];
    #pragma unroll
    for (int i = 0; i < 16; ++i) a[i] = 0.f;
    for (int s = 0; s < S; ++s) {
        const uint32_t base = ((uint32_t)sidx[rg][s] << 10) | lo;
        const uint4 v0 = *(const uint4*)(F + base);
        const uint4 v1 = *(const uint4*)(F + base + 16);
        const uint32_t w[8] = {v0.x, v0.y, v0.z, v0.w, v1.x, v1.y, v1.z, v1.w};
        #pragma unroll
        for (int j = 0; j < 8; ++j) {
            float2 f = __half22float2(*reinterpret_cast<const __half2*>(&w[j]));
            a[2 * j]     += f.x;
            a[2 * j + 1] += f.y;
        }
    }
    const float inv = 1.0f / (float)S;
    uint4 o0, o1;
    o0.x = packh2(a[0] * inv,  a[1] * inv);
    o0.y = packh2(a[2] * inv,  a[3] * inv);
    o0.z = packh2(a[4] * inv,  a[5] * inv);
    o0.w = packh2(a[6] * inv,  a[7] * inv);
    o1.x = packh2(a[8] * inv,  a[9] * inv);
    o1.y = packh2(a[10] * inv, a[11] * inv);
    o1.z = packh2(a[12] * inv, a[13] * inv);
    o1.w = packh2(a[14] * inv, a[15] * inv);
    A4[(size_t)n * 128 + 64 + 2 * lane]     = o0;
    A4[(size_t)n * 128 + 64 + 2 * lane + 1] = o1;
}

// ------------------------- kernel 1b: W f32 -> fp16 ------------------------
__global__ __launch_bounds__(256)
void wconv_kernel(const float* __restrict__ W) {
    const int i = blockIdx.x * 256 + threadIdx.x;    // over DD*KK/8
    const float4 v0 = *(const float4*)(W + (size_t)i * 8);
    const float4 v1 = *(const float4*)(W + (size_t)i * 8 + 4);
    uint4 o;
    o.x = packh2(v0.x, v0.y);
    o.y = packh2(v0.z, v0.w);
    o.z = packh2(v1.x, v1.y);
    o.w = packh2(v1.z, v1.w);
    ((uint4*)g_W16)[i] = o;
}

// ------------------------- kernel 2: HMMA GEMM + bias + ReLU + BN partials -
#define SASTRIDE 80
#define VARB     10240
#define STAGEB   (2 * VARB)
#define NSTAGE   3
#define HDRB     1024
#define GEMM_SMEM (HDRB + NSTAGE * STAGEB)   // 62464 -> 2 CTAs/SM

__global__ __launch_bounds__(256, 2)
void gemm_tc_kernel(const float* __restrict__ bias, int M) {
    extern __shared__ char smem[];
    const uint32_t sb = smem_u32(smem);
    const int tid  = threadIdx.x;
    const int wid  = tid >> 5;
    const int lane = tid & 31;
    const int wm   = wid >> 2;
    const int wn   = wid & 3;
    const int m0 = blockIdx.y * 128;
    const int n0 = blockIdx.x * 128;

    float* bsm = (float*)smem;
    if (tid < 128) bsm[tid] = bias[n0 + tid];

    const uint32_t aOff = (uint32_t)((lane & 15) * SASTRIDE + (lane >> 4) * 16);
    const uint32_t bOff = (uint32_t)(((lane & 7) + ((lane >> 4) << 3)) * SASTRIDE
                                     + (((lane >> 3) & 1) << 4));

    const char* pA = (const char*)g_A;
    const char* pW = (const char*)g_W16;

    auto load_chunk = [&](int stage, int kc) {
        const uint32_t base = sb + HDRB + stage * STAGEB;
        #pragma unroll
        for (int i = 0; i < 2; ++i) {
            const int idx = tid + (i << 8);
            const int r = idx >> 2, c = idx & 3;
            const uint32_t dst = base + (uint32_t)(r * SASTRIDE + c * 16);
            const size_t sa  = ((size_t)(m0 + r) << 11) + (size_t)(kc * 64 + c * 16);
            const size_t sbo = ((size_t)(n0 + r) << 11) + (size_t)(kc * 64 + c * 16);
            cpasync16(dst,        pA + sa);
            cpasync16(dst + VARB, pW + sbo);
        }
        cp_commit();
    };

    float acc[4][4][4];
    #pragma unroll
    for (int i = 0; i < 4; ++i)
        #pragma unroll
        for (int j = 0; j < 4; ++j)
            #pragma unroll
            for (int q = 0; q < 4; ++q) acc[i][j][q] = 0.f;

    load_chunk(0, 0);
    load_chunk(1, 1);

    const int NKC = KK / 32;
    for (int kc = 0; kc < NKC; ++kc) {
        asm volatile("cp.async.wait_group 1;" ::: "memory");
        __syncthreads();

        if (kc + 2 < NKC) load_chunk((kc + 2) % 3, kc + 2);
        else              cp_commit();

        const uint32_t st = sb + HDRB + (kc % 3) * STAGEB;
        const uint32_t bufA = st;
        const uint32_t bufB = st + VARB;

        #pragma unroll
        for (int k16 = 0; k16 < 2; ++k16) {
            const uint32_t kb = (uint32_t)(k16 * 32);
            uint32_t a[4][4], bfr[2][4];
            #pragma unroll
            for (int j2 = 0; j2 < 2; ++j2) {
                const uint32_t ro = (uint32_t)((wn * 32 + j2 * 16) * SASTRIDE) + kb;
                ldsm4(bfr[j2][0], bfr[j2][1], bfr[j2][2], bfr[j2][3], bufB + ro + bOff);
            }
            #pragma unroll
            for (int im = 0; im < 4; ++im) {
                const uint32_t ro = (uint32_t)((wm * 64 + im * 16) * SASTRIDE) + kb;
                ldsm4(a[im][0], a[im][1], a[im][2], a[im][3], bufA + ro + aOff);
            }
            #pragma unroll
            for (int im = 0; im < 4; ++im)
                #pragma unroll
                for (int jn = 0; jn < 4; ++jn)
                    mma16816(acc[im][jn], a[im], &bfr[jn >> 1][(jn & 1) * 2]);
        }
    }

    // ---- epilogue: bias + relu -> g_Hh (fp16), plus BN partial sums ----
    __syncthreads();
    float* psum = (float*)(smem + HDRB);            // [128 cols][16 slots]
    float* psq  = (float*)(smem + HDRB + 8192);
    const int g    = lane >> 2;
    const int tq   = lane & 3;
    const int slot = wm * 8 + g;

    #pragma unroll
    for (int jn = 0; jn < 4; ++jn) {
        const int colL = wn * 32 + jn * 8 + tq * 2;
        const float b0 = bsm[colL], b1 = bsm[colL + 1];
        float s0 = 0.f, s1 = 0.f, q0 = 0.f, q1 = 0.f;
        #pragma unroll
        for (int im = 0; im < 4; ++im) {
            const int row0 = m0 + wm * 64 + im * 16 + g;
            float v0 = acc[im][jn][0] + b0;
            float v1 = acc[im][jn][1] + b1;
            float v2 = acc[im][jn][2] + b0;
            float v3 = acc[im][jn][3] + b1;
            v0 = v0 > 0.f ? v0 : 0.f;
            v1 = v1 > 0.f ? v1 : 0.f;
            v2 = v2 > 0.f ? v2 : 0.f;
            v3 = v3 > 0.f ? v3 : 0.f;
            const int col = n0 + colL;
            if (row0 < M) {
                *(uint32_t*)(g_Hh + (size_t)row0 * DD + col) = packh2(v0, v1);
                s0 += v0; s1 += v1; q0 += v0 * v0; q1 += v1 * v1;
            }
            if (row0 + 8 < M) {
                *(uint32_t*)(g_Hh + (size_t)(row0 + 8) * DD + col) = packh2(v2, v3);
                s0 += v2; s1 += v3; q0 += v2 * v2; q1 += v3 * v3;
            }
        }
        psum[colL * 16 + slot]       = s0;
        psum[(colL + 1) * 16 + slot] = s1;
        psq [colL * 16 + slot]       = q0;
        psq [(colL + 1) * 16 + slot] = q1;
    }
    __syncthreads();

    {
        const int col = tid & 127;
        const float* src = (tid & 128) ? psq : psum;
        float s = 0.f;
        #pragma unroll
        for (int k = 0; k < 16; ++k) s += src[col * 16 + k];
        float* dstg = (tid & 128) ? g_psumsq : g_psum;
        dstg[blockIdx.y * DD + n0 + col] = s;
    }
}

// ------------------------- BN finalize -------------------------------------
__global__ __launch_bounds__(256)
void finalize_stats(const float* __restrict__ gamma,
                    const float* __restrict__ beta, int M, int nblk) {
    const int col  = blockIdx.x * 8 + (threadIdx.x >> 5);
    const int lane = threadIdx.x & 31;
    float s = 0.f, q = 0.f;
    for (int i = lane; i < nblk; i += 32) {
        s += g_psum  [i * DD + col];
        q += g_psumsq[i * DD + col];
    }
    #pragma unroll
    for (int o = 16; o > 0; o >>= 1) {
        s += __shfl_xor_sync(0xffffffffu, s, o);
        q += __shfl_xor_sync(0xffffffffu, q, o);
    }
    if (lane == 0) {
        const float invM = 1.0f / (float)M;
        const float mean = s * invM;
        const float var  = q * invM - mean * mean;
        const float rstd = rsqrtf(var + 1e-5f);
        const float sc = rstd * gamma[col];
        g_scale[col] = sc;
        g_shift[col] = beta[col] - mean * sc;
    }
}

// ------------------------- kernel 4: BN apply + row L2 normalize -----------
// 2 rows per 256-thread block; reads fp16 H
__global__ __launch_bounds__(256)
void bn_l2_kernel(float4* __restrict__ out4, int M) {
    const int rg = threadIdx.x >> 7;      // 0..1 row-in-block
    const int t  = threadIdx.x & 127;     // owns 4 cols
    const int n  = blockIdx.x * 2 + rg;
    const bool act = (n < M);

    const uint2*  H2  = reinterpret_cast<const uint2*>(g_Hh);
    const float4* sc4 = reinterpret_cast<const float4*>(g_scale);
    const float4* sh4 = reinterpret_cast<const float4*>(g_shift);

    float4 y = make_float4(0.f, 0.f, 0.f, 0.f);
    if (act) {
        uint2 hv = H2[(size_t)n * 128 + t];
        float2 f0 = __half22float2(*reinterpret_cast<const __half2*>(&hv.x));
        float2 f1 = __half22float2(*reinterpret_cast<const __half2*>(&hv.y));
        float4 sc = sc4[t];
        float4 sh = sh4[t];
        y.x = f0.x * sc.x + sh.x;
        y.y = f0.y * sc.y + sh.y;
        y.z = f1.x * sc.z + sh.z;
        y.w = f1.y * sc.w + sh.w;
    }

    float ss = y.x * y.x + y.y * y.y + y.z * y.z + y.w * y.w;
    #pragma unroll
    for (int o = 16; o > 0; o >>= 1)
        ss += __shfl_xor_sync(0xffffffffu, ss, o);

    __shared__ float ws[2][4];
    if ((t & 31) == 0) ws[rg][t >> 5] = ss;
    __syncthreads();
    const float tot = ws[rg][0] + ws[rg][1] + ws[rg][2] + ws[rg][3];
    const float inv = 1.0f / (sqrtf(tot) + 1e-6f);

    if (act) {
        y.x *= inv; y.y *= inv; y.z *= inv; y.w *= inv;
        out4[(size_t)n * 128 + t] = y;
    }
}

// ------------------------- launcher ----------------------------------------
extern "C" void kernel_launch(void* const* d_in, const int* in_sizes, int n_in,
                              void* d_out, int out_size) {
    const float* features = (const float*)d_in[0];
    const float* W        = (const float*)d_in[1];
    const float* b        = (const float*)d_in[2];
    const float* gamma    = (const float*)d_in[3];
    const float* beta     = (const float*)d_in[4];
    const void*  self_idx = d_in[5];
    const void*  neigh_idx= d_in[6];

    const int N = in_sizes[5];
    const int S = in_sizes[6] / N;
    const int total8 = in_sizes[0] / 8;

    cudaFuncSetAttribute(gemm_tc_kernel,
                         cudaFuncAttributeMaxDynamicSharedMemorySize, GEMM_SMEM);

    detect_idx_kernel<<<1, 256>>>((const unsigned int*)self_idx, N);
    fconv_kernel<<<(total8 + 255) / 256, 256>>>((const float4*)features, total8);
    wconv_kernel<<<(DD * KK / 8) / 256, 256>>>(W);
    agg_kernel<<<(N + 7) / 8, 256>>>(self_idx, neigh_idx, N, S);

    dim3 ggrid(DD / 128, (N + 127) / 128);
    gemm_tc_kernel<<<ggrid, 256, GEMM_SMEM>>>(b, N);

    const int nblk = (N + 127) / 128;
    finalize_stats<<<64, 256>>>(gamma, beta, N, nblk);

    bn_l2_kernel<<<(N + 1) / 2, 256>>>((float4*)d_out, N);
}

// round 13
// speedup vs baseline: 1.4872x; 1.1231x over previous
#include <cuda_runtime.h>
#include <cuda_fp16.h>
#include <cstdint>
#include <cstddef>

// ---------------------------------------------------------------------------
// SAGEConv: gather+mean-agg -> concat -> Linear(1024->512)+ReLU -> BatchNorm
//           -> row L2 normalize.
// R13: GEMM gathers self-half of A directly from the fp16 feature table
//      (no self-copy pass); agg writes only the aggregated half; merged
//      prep kernel; fp16 H; single-pass fp16 HMMA GEMM + fused BN stats.
// ---------------------------------------------------------------------------

#define DD      512
#define KK      1024
#define NMAX    20000
#define NTOT    40000
#define NPAD    20096           // 157 * 128
#define MAXBLK  640

// ------------------------- device scratch (no mallocs) ---------------------
__device__ __align__(16) __half g_F16[(size_t)NTOT * DD];   // fp16 features 41 MB
__device__ __align__(16) __half g_Agg[(size_t)NPAD * DD];   // aggregated    20 MB
__device__ __align__(16) __half g_W16[(size_t)DD * KK];     // fp16 W         1 MB
__device__ __align__(16) __half g_Hh[(size_t)NMAX * DD];    // post-ReLU fp16 20 MB
__device__ float g_psum  [MAXBLK * DD];
__device__ float g_psumsq[MAXBLK * DD];
__device__ __align__(16) float g_scale[DD];
__device__ __align__(16) float g_shift[DD];
__device__ int   g_idx_is64;

// ------------------------- helpers -----------------------------------------
__device__ __forceinline__ uint32_t smem_u32(const void* p) {
    uint32_t a;
    asm("{ .reg .u64 t; cvta.to.shared.u64 t, %1; cvt.u32.u64 %0, t; }"
        : "=r"(a) : "l"(p));
    return a;
}
__device__ __forceinline__ void cpasync16(uint32_t dst, const void* src) {
    asm volatile("cp.async.cg.shared.global [%0], [%1], 16;"
                 :: "r"(dst), "l"(src) : "memory");
}
__device__ __forceinline__ void cp_commit() {
    asm volatile("cp.async.commit_group;" ::: "memory");
}
__device__ __forceinline__ void ldsm4(uint32_t& r0, uint32_t& r1,
                                      uint32_t& r2, uint32_t& r3, uint32_t a) {
    asm volatile("ldmatrix.sync.aligned.m8n8.x4.shared.b16 {%0,%1,%2,%3}, [%4];"
                 : "=r"(r0), "=r"(r1), "=r"(r2), "=r"(r3) : "r"(a));
}
__device__ __forceinline__ void mma16816(float* d, const uint32_t* a,
                                         const uint32_t* b) {
    asm volatile(
        "mma.sync.aligned.m16n8k16.row.col.f32.f16.f16.f32 "
        "{%0,%1,%2,%3}, {%4,%5,%6,%7}, {%8,%9}, {%0,%1,%2,%3};"
        : "+f"(d[0]), "+f"(d[1]), "+f"(d[2]), "+f"(d[3])
        : "r"(a[0]), "r"(a[1]), "r"(a[2]), "r"(a[3]), "r"(b[0]), "r"(b[1]));
}
__device__ __forceinline__ uint32_t packh2(float x0, float x1) {
    __half2 h = __floats2half2_rn(x0, x1);
    return *reinterpret_cast<uint32_t*>(&h);
}
__device__ __forceinline__ long long load_idx(const void* p, size_t i, int is64) {
    if (is64) return ((const long long*)p)[i];
    return (long long)((const int*)p)[i];
}

// ------------------------- kernel 0: merged prep ---------------------------
// block 0: index dtype detect. blocks [1,1+nF): features f32->fp16.
// blocks [1+nF,1+nF+nW): W f32->fp16.
__global__ __launch_bounds__(256)
void prep_kernel(const unsigned int* __restrict__ idxw, int n,
                 const float4* __restrict__ feat4, int total8,
                 const float* __restrict__ W, int nF) {
    const int b = blockIdx.x;
    if (b == 0) {
        __shared__ unsigned int red[256];
        unsigned int acc = 0;
        for (int i = threadIdx.x; i < n; i += blockDim.x)
            if (i & 1) acc |= idxw[i];
        red[threadIdx.x] = acc;
        __syncthreads();
        for (int s = 128; s > 0; s >>= 1) {
            if (threadIdx.x < s) red[threadIdx.x] |= red[threadIdx.x + s];
            __syncthreads();
        }
        if (threadIdx.x == 0) g_idx_is64 = (red[0] == 0u) ? 1 : 0;
        return;
    }
    if (b <= nF) {
        const int i = (b - 1) * 256 + threadIdx.x;
        if (i >= total8) return;
        const float4 v0 = feat4[2 * i];
        const float4 v1 = feat4[2 * i + 1];
        uint4 o;
        o.x = packh2(v0.x, v0.y);
        o.y = packh2(v0.z, v0.w);
        o.z = packh2(v1.x, v1.y);
        o.w = packh2(v1.z, v1.w);
        ((uint4*)g_F16)[i] = o;
        return;
    }
    {
        const int i = (b - 1 - nF) * 256 + threadIdx.x;   // over DD*KK/8
        const float4 v0 = *(const float4*)(W + (size_t)i * 8);
        const float4 v1 = *(const float4*)(W + (size_t)i * 8 + 4);
        uint4 o;
        o.x = packh2(v0.x, v0.y);
        o.y = packh2(v0.z, v0.w);
        o.z = packh2(v1.x, v1.y);
        o.w = packh2(v1.z, v1.w);
        ((uint4*)g_W16)[i] = o;
    }
}

// ------------------------- kernel 1: gather(fp16) + mean agg ---------------
// 256 threads = 4 rows x 64 lanes; each lane owns 16B. f32 accumulate.
// Writes ONLY the aggregated half (g_Agg, row = 512 halfs = 1KB).
__global__ __launch_bounds__(256)
void agg_kernel(const void* __restrict__ neigh_idx, int N, int S) {
    const int rg   = threadIdx.x >> 6;    // 0..3 row-in-block
    const int lane = threadIdx.x & 63;    // 16B column
    const int n    = blockIdx.x * 4 + rg;
    __shared__ int sidx[4][32];
    const int is64 = g_idx_is64;

    for (int i = threadIdx.x; i < 4 * S; i += 256) {
        const int r = i / S, s = i - r * S;
        const int row = blockIdx.x * 4 + r;
        if (row < N)
            sidx[r][s] = (int)load_idx(neigh_idx, (size_t)row * S + s, is64);
    }
    __syncthreads();
    if (n >= N) return;

    const char* F = (const char*)g_F16;
    const uint32_t lo = (uint32_t)(lane << 4);

    float a0 = 0.f, a1 = 0.f, a2 = 0.f, a3 = 0.f;
    float a4 = 0.f, a5 = 0.f, a6 = 0.f, a7 = 0.f;
    #pragma unroll 5
    for (int s = 0; s < S; ++s) {
        const uint4 v = *(const uint4*)(F + (((uint32_t)sidx[rg][s] << 10) | lo));
        float2 f0 = __half22float2(*reinterpret_cast<const __half2*>(&v.x));
        float2 f1 = __half22float2(*reinterpret_cast<const __half2*>(&v.y));
        float2 f2 = __half22float2(*reinterpret_cast<const __half2*>(&v.z));
        float2 f3 = __half22float2(*reinterpret_cast<const __half2*>(&v.w));
        a0 += f0.x; a1 += f0.y; a2 += f1.x; a3 += f1.y;
        a4 += f2.x; a5 += f2.y; a6 += f3.x; a7 += f3.y;
    }
    const float inv = 1.0f / (float)S;
    uint4 o;
    o.x = packh2(a0 * inv, a1 * inv);
    o.y = packh2(a2 * inv, a3 * inv);
    o.z = packh2(a4 * inv, a5 * inv);
    o.w = packh2(a6 * inv, a7 * inv);
    ((uint4*)g_Agg)[(size_t)n * 64 + lane] = o;
}

// ------------------------- kernel 2: HMMA GEMM + bias + ReLU + BN partials -
// A row m = concat( F16[self_idx[m]] (cols 0..511), Agg[m] (cols 512..1023) )
// A-tile K-chunks 0..15 gathered straight from g_F16 via per-row addresses.
#define SASTRIDE 80
#define VARB     10240
#define STAGEB   (2 * VARB)
#define NSTAGE   3
#define HDRB     1024
#define GEMM_SMEM (HDRB + NSTAGE * STAGEB)   // 62464 -> 2 CTAs/SM

__global__ __launch_bounds__(256, 2)
void gemm_tc_kernel(const float* __restrict__ bias,
                    const void* __restrict__ self_idx, int M) {
    extern __shared__ char smem[];
    const uint32_t sb = smem_u32(smem);
    const int tid  = threadIdx.x;
    const int wid  = tid >> 5;
    const int lane = tid & 31;
    const int wm   = wid >> 2;
    const int wn   = wid & 3;
    const int m0 = blockIdx.y * 128;
    const int n0 = blockIdx.x * 128;

    float*     bsm     = (float*)smem;                 // [128] bias
    uint32_t*  selfoff = (uint32_t*)(smem + 512);      // [128] byte offsets
    if (tid < 128) {
        bsm[tid] = bias[n0 + tid];
        const int row = m0 + tid;
        const int si = (row < M) ? (int)load_idx(self_idx, row, g_idx_is64) : 0;
        selfoff[tid] = (uint32_t)si << 10;
    }
    __syncthreads();

    const uint32_t aOff = (uint32_t)((lane & 15) * SASTRIDE + (lane >> 4) * 16);
    const uint32_t bOff = (uint32_t)(((lane & 7) + ((lane >> 4) << 3)) * SASTRIDE
                                     + (((lane >> 3) & 1) << 4));

    const char* pF = (const char*)g_F16;
    const char* pG = (const char*)g_Agg;
    const char* pW = (const char*)g_W16;

    auto load_chunk = [&](int stage, int kc) {
        const uint32_t base = sb + HDRB + stage * STAGEB;
        #pragma unroll
        for (int i = 0; i < 2; ++i) {
            const int idx = tid + (i << 8);
            const int r = idx >> 2, c = idx & 3;
            const uint32_t dst = base + (uint32_t)(r * SASTRIDE + c * 16);
            const char* srcA;
            if (kc < 16)
                srcA = pF + (size_t)selfoff[r] + (uint32_t)(kc * 64 + c * 16);
            else
                srcA = pG + (((size_t)(m0 + r)) << 10)
                          + (uint32_t)((kc - 16) * 64 + c * 16);
            cpasync16(dst, srcA);
            const size_t sbo = ((size_t)(n0 + r) << 11) + (size_t)(kc * 64 + c * 16);
            cpasync16(dst + VARB, pW + sbo);
        }
        cp_commit();
    };

    float acc[4][4][4];
    #pragma unroll
    for (int i = 0; i < 4; ++i)
        #pragma unroll
        for (int j = 0; j < 4; ++j)
            #pragma unroll
            for (int q = 0; q < 4; ++q) acc[i][j][q] = 0.f;

    load_chunk(0, 0);
    load_chunk(1, 1);

    const int NKC = KK / 32;
    for (int kc = 0; kc < NKC; ++kc) {
        asm volatile("cp.async.wait_group 1;" ::: "memory");
        __syncthreads();

        if (kc + 2 < NKC) load_chunk((kc + 2) % 3, kc + 2);
        else              cp_commit();

        const uint32_t st = sb + HDRB + (kc % 3) * STAGEB;
        const uint32_t bufA = st;
        const uint32_t bufB = st + VARB;

        #pragma unroll
        for (int k16 = 0; k16 < 2; ++k16) {
            const uint32_t kb = (uint32_t)(k16 * 32);
            uint32_t a[4][4], bfr[2][4];
            #pragma unroll
            for (int j2 = 0; j2 < 2; ++j2) {
                const uint32_t ro = (uint32_t)((wn * 32 + j2 * 16) * SASTRIDE) + kb;
                ldsm4(bfr[j2][0], bfr[j2][1], bfr[j2][2], bfr[j2][3], bufB + ro + bOff);
            }
            #pragma unroll
            for (int im = 0; im < 4; ++im) {
                const uint32_t ro = (uint32_t)((wm * 64 + im * 16) * SASTRIDE) + kb;
                ldsm4(a[im][0], a[im][1], a[im][2], a[im][3], bufA + ro + aOff);
            }
            #pragma unroll
            for (int im = 0; im < 4; ++im)
                #pragma unroll
                for (int jn = 0; jn < 4; ++jn)
                    mma16816(acc[im][jn], a[im], &bfr[jn >> 1][(jn & 1) * 2]);
        }
    }

    // ---- epilogue: bias + relu -> g_Hh (fp16), plus BN partial sums ----
    __syncthreads();
    float* psum = (float*)(smem + HDRB);            // [128 cols][16 slots]
    float* psq  = (float*)(smem + HDRB + 8192);
    const int g    = lane >> 2;
    const int tq   = lane & 3;
    const int slot = wm * 8 + g;

    #pragma unroll
    for (int jn = 0; jn < 4; ++jn) {
        const int colL = wn * 32 + jn * 8 + tq * 2;
        const float b0 = bsm[colL], b1 = bsm[colL + 1];
        float s0 = 0.f, s1 = 0.f, q0 = 0.f, q1 = 0.f;
        #pragma unroll
        for (int im = 0; im < 4; ++im) {
            const int row0 = m0 + wm * 64 + im * 16 + g;
            float v0 = acc[im][jn][0] + b0;
            float v1 = acc[im][jn][1] + b1;
            float v2 = acc[im][jn][2] + b0;
            float v3 = acc[im][jn][3] + b1;
            v0 = v0 > 0.f ? v0 : 0.f;
            v1 = v1 > 0.f ? v1 : 0.f;
            v2 = v2 > 0.f ? v2 : 0.f;
            v3 = v3 > 0.f ? v3 : 0.f;
            const int col = n0 + colL;
            if (row0 < M) {
                *(uint32_t*)(g_Hh + (size_t)row0 * DD + col) = packh2(v0, v1);
                s0 += v0; s1 += v1; q0 += v0 * v0; q1 += v1 * v1;
            }
            if (row0 + 8 < M) {
                *(uint32_t*)(g_Hh + (size_t)(row0 + 8) * DD + col) = packh2(v2, v3);
                s0 += v2; s1 += v3; q0 += v2 * v2; q1 += v3 * v3;
            }
        }
        psum[colL * 16 + slot]       = s0;
        psum[(colL + 1) * 16 + slot] = s1;
        psq [colL * 16 + slot]       = q0;
        psq [(colL + 1) * 16 + slot] = q1;
    }
    __syncthreads();

    {
        const int col = tid & 127;
        const float* src = (tid & 128) ? psq : psum;
        float s = 0.f;
        #pragma unroll
        for (int k = 0; k < 16; ++k) s += src[col * 16 + k];
        float* dstg = (tid & 128) ? g_psumsq : g_psum;
        dstg[blockIdx.y * DD + n0 + col] = s;
    }
}

// ------------------------- BN finalize -------------------------------------
__global__ __launch_bounds__(256)
void finalize_stats(const float* __restrict__ gamma,
                    const float* __restrict__ beta, int M, int nblk) {
    const int col  = blockIdx.x * 8 + (threadIdx.x >> 5);
    const int lane = threadIdx.x & 31;
    float s = 0.f, q = 0.f;
    for (int i = lane; i < nblk; i += 32) {
        s += g_psum  [i * DD + col];
        q += g_psumsq[i * DD + col];
    }
    #pragma unroll
    for (int o = 16; o > 0; o >>= 1) {
        s += __shfl_xor_sync(0xffffffffu, s, o);
        q += __shfl_xor_sync(0xffffffffu, q, o);
    }
    if (lane == 0) {
        const float invM = 1.0f / (float)M;
        const float mean = s * invM;
        const float var  = q * invM - mean * mean;
        const float rstd = rsqrtf(var + 1e-5f);
        const float sc = rstd * gamma[col];
        g_scale[col] = sc;
        g_shift[col] = beta[col] - mean * sc;
    }
}

// ------------------------- kernel 4: BN apply + row L2 normalize -----------
__global__ __launch_bounds__(256)
void bn_l2_kernel(float4* __restrict__ out4, int M) {
    const int rg = threadIdx.x >> 7;      // 0..1 row-in-block
    const int t  = threadIdx.x & 127;     // owns 4 cols
    const int n  = blockIdx.x * 2 + rg;
    const bool act = (n < M);

    const uint2*  H2  = reinterpret_cast<const uint2*>(g_Hh);
    const float4* sc4 = reinterpret_cast<const float4*>(g_scale);
    const float4* sh4 = reinterpret_cast<const float4*>(g_shift);

    float4 y = make_float4(0.f, 0.f, 0.f, 0.f);
    if (act) {
        uint2 hv = H2[(size_t)n * 128 + t];
        float2 f0 = __half22float2(*reinterpret_cast<const __half2*>(&hv.x));
        float2 f1 = __half22float2(*reinterpret_cast<const __half2*>(&hv.y));
        float4 sc = sc4[t];
        float4 sh = sh4[t];
        y.x = f0.x * sc.x + sh.x;
        y.y = f0.y * sc.y + sh.y;
        y.z = f1.x * sc.z + sh.z;
        y.w = f1.y * sc.w + sh.w;
    }

    float ss = y.x * y.x + y.y * y.y + y.z * y.z + y.w * y.w;
    #pragma unroll
    for (int o = 16; o > 0; o >>= 1)
        ss += __shfl_xor_sync(0xffffffffu, ss, o);

    __shared__ float ws[2][4];
    if ((t & 31) == 0) ws[rg][t >> 5] = ss;
    __syncthreads();
    const float tot = ws[rg][0] + ws[rg][1] + ws[rg][2] + ws[rg][3];
    const float inv = 1.0f / (sqrtf(tot) + 1e-6f);

    if (act) {
        y.x *= inv; y.y *= inv; y.z *= inv; y.w *= inv;
        out4[(size_t)n * 128 + t] = y;
    }
}

// ------------------------- launcher ----------------------------------------
extern "C" void kernel_launch(void* const* d_in, const int* in_sizes, int n_in,
                              void* d_out, int out_size) {
    const float* features = (const float*)d_in[0];
    const float* W        = (const float*)d_in[1];
    const float* b        = (const float*)d_in[2];
    const float* gamma    = (const float*)d_in[3];
    const float* beta     = (const float*)d_in[4];
    const void*  self_idx = d_in[5];
    const void*  neigh_idx= d_in[6];

    const int N = in_sizes[5];
    const int S = in_sizes[6] / N;
    const int total8 = in_sizes[0] / 8;
    const int nF = (total8 + 255) / 256;
    const int nW = (DD * KK / 8) / 256;

    cudaFuncSetAttribute(gemm_tc_kernel,
                         cudaFuncAttributeMaxDynamicSharedMemorySize, GEMM_SMEM);

    prep_kernel<<<1 + nF + nW, 256>>>((const unsigned int*)self_idx, N,
                                      (const float4*)features, total8, W, nF);
    agg_kernel<<<(N + 3) / 4, 256>>>(neigh_idx, N, S);

    dim3 ggrid(DD / 128, (N + 127) / 128);
    gemm_tc_kernel<<<ggrid, 256, GEMM_SMEM>>>(b, self_idx, N);

    const int nblk = (N + 127) / 128;
    finalize_stats<<<64, 256>>>(gamma, beta, N, nblk);

    bn_l2_kernel<<<(N + 1) / 2, 256>>>((float4*)d_out, N);
}